// round 10
// baseline (speedup 1.0000x reference)
#include <cuda_runtime.h>

// x [4194304, 8] fp32. Keep row iff expert 0 is in the row's top-2
// (top_k ties break low-index -> expert 0), else zero it.
// Predicate: count(x[j] > x[0], j=1..7) <= 1.
//
// Persistent grid-stride streaming kernel:
//  - 1216 CTAs (152 SMs x occ 8), single wave, no wave-transition overhead
//  - 4 rows per loop iteration at grid-stride offsets -> 8 independent
//    LDG.128 front-batched per iteration (MLP_p1 = 8)
//  - __ldcs/__stcs: touch-once data, evict-first, keep L2 out of the way
// HBM-bound: 256 MiB traffic; target ~6.7 TB/s -> ~31 us.

__device__ __forceinline__ void process_row(const float4* __restrict__ in,
                                            float4* __restrict__ out,
                                            int row)
{
    float4 a = __ldcs(&in[2 * row]);       // x[0..3]
    float4 b = __ldcs(&in[2 * row + 1]);   // x[4..7]

    float x0 = a.x;
    int cnt = (a.y > x0) + (a.z > x0) + (a.w > x0)
            + (b.x > x0) + (b.y > x0) + (b.z > x0) + (b.w > x0);

    float keep = (cnt <= 1) ? 1.0f : 0.0f;

    float4 ra, rb;
    ra.x = a.x * keep;  ra.y = a.y * keep;
    ra.z = a.z * keep;  ra.w = a.w * keep;
    rb.x = b.x * keep;  rb.y = b.y * keep;
    rb.z = b.z * keep;  rb.w = b.w * keep;

    __stcs(&out[2 * row],     ra);
    __stcs(&out[2 * row + 1], rb);
}

__global__ void __launch_bounds__(256)
routing_e0_kernel(const float4* __restrict__ in,
                  float4* __restrict__ out,
                  int nrows)
{
    const int stride = gridDim.x * blockDim.x;
    int row = blockIdx.x * blockDim.x + threadIdx.x;

    // Main loop: 4 rows per iteration, loads front-batched by the compiler
    // (independent rows -> 8 outstanding LDG.128 before first use).
    for (; row + 3 * stride < nrows; row += 4 * stride) {
        int r0 = row;
        int r1 = row + stride;
        int r2 = row + 2 * stride;
        int r3 = row + 3 * stride;

        float4 a0 = __ldcs(&in[2 * r0]), b0 = __ldcs(&in[2 * r0 + 1]);
        float4 a1 = __ldcs(&in[2 * r1]), b1 = __ldcs(&in[2 * r1 + 1]);
        float4 a2 = __ldcs(&in[2 * r2]), b2 = __ldcs(&in[2 * r2 + 1]);
        float4 a3 = __ldcs(&in[2 * r3]), b3 = __ldcs(&in[2 * r3 + 1]);

        #define ROUTE_EMIT(A, B, R)                                          \
        {                                                                    \
            float x0 = (A).x;                                                \
            int cnt = ((A).y > x0) + ((A).z > x0) + ((A).w > x0)             \
                    + ((B).x > x0) + ((B).y > x0) + ((B).z > x0)             \
                    + ((B).w > x0);                                          \
            float keep = (cnt <= 1) ? 1.0f : 0.0f;                           \
            float4 ra, rb;                                                   \
            ra.x = (A).x * keep; ra.y = (A).y * keep;                        \
            ra.z = (A).z * keep; ra.w = (A).w * keep;                        \
            rb.x = (B).x * keep; rb.y = (B).y * keep;                        \
            rb.z = (B).z * keep; rb.w = (B).w * keep;                        \
            __stcs(&out[2 * (R)],     ra);                                   \
            __stcs(&out[2 * (R) + 1], rb);                                   \
        }

        ROUTE_EMIT(a0, b0, r0);
        ROUTE_EMIT(a1, b1, r1);
        ROUTE_EMIT(a2, b2, r2);
        ROUTE_EMIT(a3, b3, r3);
        #undef ROUTE_EMIT
    }

    // Tail
    for (; row < nrows; row += stride)
        process_row(in, out, row);
}

extern "C" void kernel_launch(void* const* d_in, const int* in_sizes, int n_in,
                              void* d_out, int out_size)
{
    const float4* in  = (const float4*)d_in[0];
    float4*       out = (float4*)d_out;

    int n_elems = in_sizes[0];     // SEQ_LEN * 8 floats
    int nrows = n_elems / 8;

    const int threads = 256;
    const int blocks  = 152 * 8;   // GB300: 152 SMs, occ 8 @ 256 thr / 16 regs
    routing_e0_kernel<<<blocks, threads>>>(in, out, nrows);
}

// round 12
// speedup vs baseline: 1.0902x; 1.0902x over previous
#include <cuda_runtime.h>

// x [4194304, 8] fp32. Keep row iff expert 0 is in the row's top-2
// (top_k ties break low-index -> expert 0), else zero it.
// Predicate: count(x[j] > x[0], j=1..7) <= 1.
//
// Flat kernel, 2 rows per thread (block-tiled): block b owns rows
// [b*512, b*512+512); thread t handles rows base+t and base+t+256.
// -> 4 independent LDG.128 front-batched per thread (MLP_p1 = 4) at
// low register cost (~32 regs), keeping occupancy at 8 CTAs/SM.
// Per-warp lane stride 32 B: every 32 B sector hit exactly once.
// HBM-bound: 256 MiB traffic; R3 (MLP_p1=2) hit 5.74 TB/s; target ~6.4 TB/s.

__global__ void __launch_bounds__(256)
routing_e0_kernel(const float4* __restrict__ in,
                  float4* __restrict__ out,
                  int nrows)
{
    int base = blockIdx.x * 512 + threadIdx.x;
    int r0 = base;
    int r1 = base + 256;
    if (r1 >= nrows) {            // uniform across the block except last block
        if (r0 >= nrows) return;
        r1 = r0;                  // degenerate: process r0 twice (idempotent)
    }

    // Front-batched independent loads: 4 outstanding LDG.128.
    float4 a0 = in[2 * r0];
    float4 b0 = in[2 * r0 + 1];
    float4 a1 = in[2 * r1];
    float4 b1 = in[2 * r1 + 1];

    float x00 = a0.x;
    int c0 = (a0.y > x00) + (a0.z > x00) + (a0.w > x00)
           + (b0.x > x00) + (b0.y > x00) + (b0.z > x00) + (b0.w > x00);
    float k0 = (c0 <= 1) ? 1.0f : 0.0f;

    float x01 = a1.x;
    int c1 = (a1.y > x01) + (a1.z > x01) + (a1.w > x01)
           + (b1.x > x01) + (b1.y > x01) + (b1.z > x01) + (b1.w > x01);
    float k1 = (c1 <= 1) ? 1.0f : 0.0f;

    float4 ra0, rb0, ra1, rb1;
    ra0.x = a0.x * k0; ra0.y = a0.y * k0; ra0.z = a0.z * k0; ra0.w = a0.w * k0;
    rb0.x = b0.x * k0; rb0.y = b0.y * k0; rb0.z = b0.z * k0; rb0.w = b0.w * k0;
    ra1.x = a1.x * k1; ra1.y = a1.y * k1; ra1.z = a1.z * k1; ra1.w = a1.w * k1;
    rb1.x = b1.x * k1; rb1.y = b1.y * k1; rb1.z = b1.z * k1; rb1.w = b1.w * k1;

    out[2 * r0]     = ra0;
    out[2 * r0 + 1] = rb0;
    out[2 * r1]     = ra1;
    out[2 * r1 + 1] = rb1;
}

extern "C" void kernel_launch(void* const* d_in, const int* in_sizes, int n_in,
                              void* d_out, int out_size)
{
    const float4* in  = (const float4*)d_in[0];
    float4*       out = (float4*)d_out;

    int n_elems = in_sizes[0];     // SEQ_LEN * 8 floats
    int nrows = n_elems / 8;       // 4194304

    const int threads = 256;
    int blocks = (nrows + 511) / 512;   // 8192 for the full shape
    routing_e0_kernel<<<blocks, threads>>>(in, out, nrows);
}